// round 14
// baseline (speedup 1.0000x reference)
#include <cuda_runtime.h>

#define NNODE 17
#define TPB   272      // 17 nodes x 16 graph-lanes
#define NG    32       // graphs per block: 2 graph-sets per thread (s = 0,1)

typedef unsigned long long u64;

// packed fp32x2 ops (Blackwell); ptxas never auto-fuses these from C++
__device__ __forceinline__ u64 ffma2(u64 a, u64 b, u64 c) {
    u64 d;
    asm("fma.rn.f32x2 %0, %1, %2, %3;" : "=l"(d) : "l"(a), "l"(b), "l"(c));
    return d;
}
__device__ __forceinline__ u64 add2(u64 a, u64 b) {
    u64 d;
    asm("add.rn.f32x2 %0, %1, %2;" : "=l"(d) : "l"(a), "l"(b));
    return d;
}
__device__ __forceinline__ u64 mul2(u64 a, u64 b) {
    u64 d;
    asm("mul.rn.f32x2 %0, %1, %2;" : "=l"(d) : "l"(a), "l"(b));
    return d;
}
__device__ __forceinline__ u64 bcast2(float v) {
    u64 d; unsigned r = __float_as_uint(v);
    asm("mov.b64 %0, {%1, %1};" : "=l"(d) : "r"(r));
    return d;
}
__device__ __forceinline__ u64 pack2(float x, float y) {
    u64 d;
    asm("mov.b64 %0, {%1, %2};" : "=l"(d) : "r"(__float_as_uint(x)), "r"(__float_as_uint(y)));
    return d;
}
__device__ __forceinline__ void unpk(u64 d, float& x, float& y) {
    unsigned a, b;
    asm("mov.b64 {%0, %1}, %2;" : "=r"(a), "=r"(b) : "l"(d));
    x = __uint_as_float(a); y = __uint_as_float(b);
}

// ---- block-invariant ring-averaged FC weights (proven in R13) ----
// a0[n] = avg over ring of (z @ fc_w)[.] = z @ Wavg[:, 8n:8n+8] + Bavg[8n:8n+8]
__device__ __align__(16) float g_fcw_avg[32 * 136];   // compact rows (LDG path)
__device__ __align__(16) float g_fb_avg[136];

__global__ void prep_avg_fc(const float* __restrict__ fc_w,
                            const float* __restrict__ fc_b) {
    int i = blockIdx.x * blockDim.x + threadIdx.x;
    if (i < 4352) {
        int k = i / 136, c = i - k * 136;
        int nn = c >> 3, j = c & 7;
        int cp = ((nn + 1)  % 17) * 8 + j;
        int cm = ((nn + 16) % 17) * 8 + j;
        g_fcw_avg[k * 136 + c] =
            (fc_w[k * 136 + cp] + fc_w[k * 136 + c] + fc_w[k * 136 + cm]) * (1.0f / 3.0f);
        if (i < 136)
            g_fb_avg[i] = (fc_b[cp] + fc_b[i] + fc_b[cm]) * (1.0f / 3.0f);
    }
}

// ---- dynamic shared layout (float offsets) — 50.8KB: 3 blocks/SM fit ----
#define W1S   0        // 8x16
#define B1S   128      // 16
#define W2S   144      // 16x32
#define B2S   656      // 32
#define W3S   688      // 32x32
#define B3S   1712     // 32
#define ZS    1744     // 32 graphs x 36
#define ARENA 2896     // 272 rows x 36 floats (exchange + out staging, per-s reuse)
#define SHFLOATS 12688 // 50752 bytes per block (x3 blocks = 152.3KB <= 228KB/SM)

extern __shared__ float sh[];

__global__ void __launch_bounds__(TPB, 3)
gnn_fused(const float* __restrict__ z,
          const float* __restrict__ w1,   const float* __restrict__ b1,
          const float* __restrict__ w2,   const float* __restrict__ b2,
          const float* __restrict__ w3,   const float* __restrict__ b3,
          float* __restrict__ out)
{
    const int tid = threadIdx.x;

    // ---------------- stage small weights + z into shared ----------------
    for (int i = tid; i < 128;  i += TPB) sh[W1S + i] = w1[i];
    for (int i = tid; i < 512;  i += TPB) sh[W2S + i] = w2[i];
    for (int i = tid; i < 1024; i += TPB) sh[W3S + i] = w3[i];
    if (tid < 16)                         sh[B1S + tid] = b1[tid];
    else if (tid >= 32 && tid < 64)       sh[B2S + tid - 32] = b2[tid - 32];
    else if (tid >= 64 && tid < 96)       sh[B3S + tid - 64] = b3[tid - 64];
    {
        const float* zblk = z + (size_t)blockIdx.x * (NG * 32);
        for (int i = tid; i < NG * 32; i += TPB)
            sh[ZS + (i >> 5) * 36 + (i & 31)] = zblk[i];
    }
    __syncthreads();                       // BAR: init

    // thread = node n, graphs g and g+16; warp holds 2 adjacent nodes x 16 lanes
    const int n  = tid >> 4;
    const int g  = tid & 15;
    const int rp = (n == NNODE - 1) ? g       : tid + 16;  // row of node (n+1)%17
    const int rm = (n == 0)         ? 256 + g : tid - 16;  // row of node (n-1)%17
    const u64 third2 = bcast2(1.0f / 3.0f);

    // ===== FC (ring-avg folded): a0 = z @ Wavg[:, 8n:8n+8] + Bavg, per-s =====
    // weights via __ldg: warp's two nodes are adjacent -> 32B contiguous/warp
    float a0[2][8];
    #pragma unroll
    for (int s = 0; s < 2; s++) {
        float zr[32];
        const float4* zp = (const float4*)(sh + ZS + (g + 16 * s) * 36);
        #pragma unroll
        for (int i = 0; i < 8; i++) {
            float4 v = zp[i];
            zr[4*i] = v.x; zr[4*i+1] = v.y; zr[4*i+2] = v.z; zr[4*i+3] = v.w;
        }
        u64 acc[4];
        {
            const u64* fb = (const u64*)g_fb_avg + n * 4;
            #pragma unroll
            for (int i = 0; i < 4; i++) acc[i] = __ldg(fb + i);
        }
        #pragma unroll
        for (int k = 0; k < 32; k++) {
            const ulonglong2* w = (const ulonglong2*)(g_fcw_avg + k * 136 + n * 8);
            ulonglong2 wa = __ldg(w), wb = __ldg(w + 1);
            u64 zz = bcast2(zr[k]);
            acc[0] = ffma2(zz, wa.x, acc[0]);
            acc[1] = ffma2(zz, wa.y, acc[1]);
            acc[2] = ffma2(zz, wb.x, acc[2]);
            acc[3] = ffma2(zz, wb.y, acc[3]);
        }
        #pragma unroll
        for (int i = 0; i < 4; i++) unpk(acc[i], a0[s][2*i], a0[s][2*i+1]);
    }

    // ================= conv1: x1 = relu(a0 @ w1 + b1), 16 out (dual-s) ========
    u64 x1p[2][8];
    {
        u64 acc[2][8];
        const u64* bb = (const u64*)(sh + B1S);
        #pragma unroll
        for (int j = 0; j < 8; j++) { u64 b = bb[j]; acc[0][j] = b; acc[1][j] = b; }
        #pragma unroll
        for (int k = 0; k < 8; k++) {
            const ulonglong2* w = (const ulonglong2*)(sh + W1S + k * 16);
            #pragma unroll
            for (int q = 0; q < 4; q++) {
                ulonglong2 t = w[q];
                #pragma unroll
                for (int s = 0; s < 2; s++) {
                    u64 av = bcast2(a0[s][k]);
                    acc[s][2*q]   = ffma2(av, t.x, acc[s][2*q]);
                    acc[s][2*q+1] = ffma2(av, t.y, acc[s][2*q+1]);
                }
            }
        }
        #pragma unroll
        for (int s = 0; s < 2; s++)
            #pragma unroll
            for (int j = 0; j < 8; j++) {
                float x, y; unpk(acc[s][j], x, y);
                x1p[s][j] = pack2(fmaxf(x, 0.0f), fmaxf(y, 0.0f));
            }
    }

    // ===== x1 ring exchange, sequential per s through 272-row arena ==========
    float a1[2][16];
    #pragma unroll
    for (int s = 0; s < 2; s++) {
        ulonglong2* row = (ulonglong2*)(sh + ARENA + tid * 36);
        #pragma unroll
        for (int q = 0; q < 4; q++)
            row[q] = make_ulonglong2(x1p[s][2*q], x1p[s][2*q+1]);
        __syncthreads();                   // x1[s] published
        const ulonglong2* p = (const ulonglong2*)(sh + ARENA + rp * 36);
        const ulonglong2* m = (const ulonglong2*)(sh + ARENA + rm * 36);
        #pragma unroll
        for (int q = 0; q < 4; q++) {
            ulonglong2 pv = p[q], mv = m[q];
            u64 t0 = mul2(add2(add2(x1p[s][2*q],   pv.x), mv.x), third2);
            u64 t1 = mul2(add2(add2(x1p[s][2*q+1], pv.y), mv.y), third2);
            unpk(t0, a1[s][4*q+0], a1[s][4*q+1]);
            unpk(t1, a1[s][4*q+2], a1[s][4*q+3]);
        }
        __syncthreads();                   // x1[s] reads done (WAR)
    }

    // ====== conv2: x2 = relu(a1 @ w2 + b2), 32 out, j-halves (dual-s) ========
    u64 x2p[2][16];
    #pragma unroll
    for (int h = 0; h < 2; h++) {
        u64 acc[2][8];
        const u64* bb = (const u64*)(sh + B2S + h * 16);
        #pragma unroll
        for (int j = 0; j < 8; j++) { u64 b = bb[j]; acc[0][j] = b; acc[1][j] = b; }
        #pragma unroll
        for (int k = 0; k < 16; k++) {
            const ulonglong2* w = (const ulonglong2*)(sh + W2S + k * 32 + h * 16);
            #pragma unroll
            for (int q = 0; q < 4; q++) {
                ulonglong2 t = w[q];
                #pragma unroll
                for (int s = 0; s < 2; s++) {
                    u64 av = bcast2(a1[s][k]);
                    acc[s][2*q]   = ffma2(av, t.x, acc[s][2*q]);
                    acc[s][2*q+1] = ffma2(av, t.y, acc[s][2*q+1]);
                }
            }
        }
        #pragma unroll
        for (int s = 0; s < 2; s++)
            #pragma unroll
            for (int j = 0; j < 8; j++) {
                float x, y; unpk(acc[s][j], x, y);
                x2p[s][h * 8 + j] = pack2(fmaxf(x, 0.0f), fmaxf(y, 0.0f));
            }
    }

    // ====== per-s: x2 exchange -> a2 -> conv3 -> stage -> gmem ================
    float4* ogbase = (float4*)(out + (size_t)blockIdx.x * (NG * NNODE * 32));
    #pragma unroll
    for (int s = 0; s < 2; s++) {
        // publish x2[s]
        {
            ulonglong2* row = (ulonglong2*)(sh + ARENA + tid * 36);
            #pragma unroll
            for (int q = 0; q < 8; q++)
                row[q] = make_ulonglong2(x2p[s][2*q], x2p[s][2*q+1]);
        }
        __syncthreads();                   // x2[s] published
        float a2s[32];
        {
            const ulonglong2* p = (const ulonglong2*)(sh + ARENA + rp * 36);
            const ulonglong2* m = (const ulonglong2*)(sh + ARENA + rm * 36);
            #pragma unroll
            for (int q = 0; q < 8; q++) {
                ulonglong2 pv = p[q], mv = m[q];
                u64 t0 = mul2(add2(add2(x2p[s][2*q],   pv.x), mv.x), third2);
                u64 t1 = mul2(add2(add2(x2p[s][2*q+1], pv.y), mv.y), third2);
                unpk(t0, a2s[4*q+0], a2s[4*q+1]);
                unpk(t1, a2s[4*q+2], a2s[4*q+3]);
            }
        }
        // conv3 h-halves; h0 compute placed before the WAR bar to absorb skew
        #pragma unroll
        for (int h = 0; h < 2; h++) {
            u64 acc[8];
            const u64* bb = (const u64*)(sh + B3S + h * 16);
            #pragma unroll
            for (int j = 0; j < 8; j++) acc[j] = bb[j];
            #pragma unroll
            for (int k = 0; k < 32; k++) {
                u64 av = bcast2(a2s[k]);
                const ulonglong2* w = (const ulonglong2*)(sh + W3S + k * 32 + h * 16);
                #pragma unroll
                for (int q = 0; q < 4; q++) {
                    ulonglong2 t = w[q];
                    acc[2*q]   = ffma2(av, t.x, acc[2*q]);
                    acc[2*q+1] = ffma2(av, t.y, acc[2*q+1]);
                }
            }
            if (h == 0) __syncthreads();   // x2[s] reads done (WAR), skew hidden
            // stage in out layout: row = g*17 + n (16 graphs of this s)
            ulonglong2* row = (ulonglong2*)(sh + ARENA + (g * 17 + n) * 36 + h * 16);
            #pragma unroll
            for (int q = 0; q < 4; q++)
                row[q] = make_ulonglong2(acc[2*q], acc[2*q+1]);
        }
        __syncthreads();                   // staging published
        // coalesced gmem write: 16*17*32 = 8704 floats = 2176 float4
        {
            float4* og = ogbase + s * 2176 + tid;
            const float* src = sh + ARENA + (tid >> 3) * 36 + (tid & 7) * 4;
            #pragma unroll
            for (int it = 0; it < 8; it++) {
                *og = *(const float4*)src;
                og  += TPB;
                src += 34 * 36;
            }
        }
        if (s == 0) __syncthreads();       // staging reads done before s1 reuse
    }
}

extern "C" void kernel_launch(void* const* d_in, const int* in_sizes, int n_in,
                              void* d_out, int out_size) {
    const float* z    = (const float*)d_in[0];
    // d_in[1] = edge_index: fixed ring, degree==3 everywhere -> norm==1/3; unused
    const float* fc_w = (const float*)d_in[2];
    const float* fc_b = (const float*)d_in[3];
    const float* w1   = (const float*)d_in[4];
    const float* b1   = (const float*)d_in[5];
    const float* w2   = (const float*)d_in[6];
    const float* b2   = (const float*)d_in[7];
    const float* w3   = (const float*)d_in[8];
    const float* b3   = (const float*)d_in[9];

    cudaFuncSetAttribute(gnn_fused, cudaFuncAttributeMaxDynamicSharedMemorySize,
                         SHFLOATS * 4);

    // pre-kernel: block-invariant ring-averaged FC weights/bias (~2us)
    prep_avg_fc<<<17, 256>>>(fc_w, fc_b);

    const int B    = in_sizes[0] / 32;      // 65536 graphs
    const int grid = B / NG;                // 2048 blocks
    gnn_fused<<<grid, TPB, SHFLOATS * 4>>>(z, w1, b1, w2, b2, w3, b3,
                                           (float*)d_out);
}

// round 15
// speedup vs baseline: 1.7145x; 1.7145x over previous
#include <cuda_runtime.h>

#define NNODE 17
#define TPB   272      // 17 nodes x 16 graph-lanes
#define NG    32       // graphs per block: 2 graph-sets per thread (s = 0,1)

typedef unsigned long long u64;

// packed fp32x2 ops (Blackwell); ptxas never auto-fuses these from C++
__device__ __forceinline__ u64 ffma2(u64 a, u64 b, u64 c) {
    u64 d;
    asm("fma.rn.f32x2 %0, %1, %2, %3;" : "=l"(d) : "l"(a), "l"(b), "l"(c));
    return d;
}
__device__ __forceinline__ u64 add2(u64 a, u64 b) {
    u64 d;
    asm("add.rn.f32x2 %0, %1, %2;" : "=l"(d) : "l"(a), "l"(b));
    return d;
}
__device__ __forceinline__ u64 mul2(u64 a, u64 b) {
    u64 d;
    asm("mul.rn.f32x2 %0, %1, %2;" : "=l"(d) : "l"(a), "l"(b));
    return d;
}
__device__ __forceinline__ u64 bcast2(float v) {
    u64 d; unsigned r = __float_as_uint(v);
    asm("mov.b64 %0, {%1, %1};" : "=l"(d) : "r"(r));
    return d;
}
__device__ __forceinline__ u64 pack2(float x, float y) {
    u64 d;
    asm("mov.b64 %0, {%1, %2};" : "=l"(d) : "r"(__float_as_uint(x)), "r"(__float_as_uint(y)));
    return d;
}
__device__ __forceinline__ void unpk(u64 d, float& x, float& y) {
    unsigned a, b;
    asm("mov.b64 {%0, %1}, %2;" : "=r"(a), "=r"(b) : "l"(d));
    x = __uint_as_float(a); y = __uint_as_float(b);
}

// ---- dynamic shared layout (float offsets) ----
#define FCS   0        // fc_w: 32 rows x 160 (136 used; warp's n-pair in one 128B line)
#define W1S   5120     // 8x16
#define B1S   5248     // 16
#define W2S   5264     // 16x32
#define B2S   5776     // 32
#define W3S   5808     // 32x32
#define B3S   6832     // 32
#define ZS    6864     // 32 graphs x 36
#define ARENA 8016     // 544 rows x 36 floats (exchange + out staging)
#define SHFLOATS 27600 // 110400 bytes per block (x2 blocks <= 228KB/SM)

extern __shared__ float sh[];

__global__ void __launch_bounds__(TPB, 2)
gnn_fused(const float* __restrict__ z,
          const float* __restrict__ fc_w, const float* __restrict__ fc_b,
          const float* __restrict__ w1,   const float* __restrict__ b1,
          const float* __restrict__ w2,   const float* __restrict__ b2,
          const float* __restrict__ w3,   const float* __restrict__ b3,
          float* __restrict__ out)
{
    const int tid = threadIdx.x;

    // ---------------- stage weights + z into shared ----------------
    for (int i = tid; i < 4352; i += TPB) {            // fc_w rows padded 136->160
        int k = i / 136, c = i - k * 136;
        sh[FCS + k * 160 + c] = fc_w[i];
    }
    for (int i = tid; i < 128;  i += TPB) sh[W1S + i] = w1[i];
    for (int i = tid; i < 512;  i += TPB) sh[W2S + i] = w2[i];
    for (int i = tid; i < 1024; i += TPB) sh[W3S + i] = w3[i];
    if (tid < 16)                         sh[B1S + tid] = b1[tid];
    else if (tid >= 32 && tid < 64)       sh[B2S + tid - 32] = b2[tid - 32];
    else if (tid >= 64 && tid < 96)       sh[B3S + tid - 64] = b3[tid - 64];
    {
        const float* zblk = z + (size_t)blockIdx.x * (NG * 32);
        for (int i = tid; i < NG * 32; i += TPB)
            sh[ZS + (i >> 5) * 36 + (i & 31)] = zblk[i];
    }
    __syncthreads();                       // BAR 0: init

    // thread = node n, graphs g and g+16; warp holds 2 nodes x 16 lanes
    const int n  = tid >> 4;
    const int g  = tid & 15;
    const int rp = (n == NNODE - 1) ? g       : tid + 16;  // row of node (n+1)%17
    const int rm = (n == 0)         ? 256 + g : tid - 16;  // row of node (n-1)%17
    const u64 third2 = bcast2(1.0f / 3.0f);

    // ================= FC: x0 = z @ fc_w[:, 8n:8n+8] + fc_b ==================
    u64 x0p[2][4];
    {
        float zr[2][32];
        #pragma unroll
        for (int s = 0; s < 2; s++) {
            const float4* zp = (const float4*)(sh + ZS + (g + 16 * s) * 36);
            #pragma unroll
            for (int i = 0; i < 8; i++) {
                float4 v = zp[i];
                zr[s][4*i] = v.x; zr[s][4*i+1] = v.y; zr[s][4*i+2] = v.z; zr[s][4*i+3] = v.w;
            }
        }
        {
            const u64* fb = (const u64*)fc_b + n * 4;
            #pragma unroll
            for (int i = 0; i < 4; i++) { u64 b = __ldg(fb + i); x0p[0][i] = b; x0p[1][i] = b; }
        }
        #pragma unroll
        for (int k = 0; k < 32; k++) {
            const ulonglong2* w = (const ulonglong2*)(sh + FCS + k * 160 + n * 8);
            ulonglong2 wa = w[0], wb = w[1];
            #pragma unroll
            for (int s = 0; s < 2; s++) {
                u64 zz = bcast2(zr[s][k]);
                x0p[s][0] = ffma2(zz, wa.x, x0p[s][0]);
                x0p[s][1] = ffma2(zz, wa.y, x0p[s][1]);
                x0p[s][2] = ffma2(zz, wb.x, x0p[s][2]);
                x0p[s][3] = ffma2(zz, wb.y, x0p[s][3]);
            }
        }
    }
    #pragma unroll
    for (int s = 0; s < 2; s++) {
        ulonglong2* row = (ulonglong2*)(sh + ARENA + (s * 272 + tid) * 36);
        row[0] = make_ulonglong2(x0p[s][0], x0p[s][1]);
        row[1] = make_ulonglong2(x0p[s][2], x0p[s][3]);
    }
    __syncthreads();                       // BAR A: x0 published

    float a0[2][8];
    #pragma unroll
    for (int s = 0; s < 2; s++) {
        const ulonglong2* p = (const ulonglong2*)(sh + ARENA + (s * 272 + rp) * 36);
        const ulonglong2* m = (const ulonglong2*)(sh + ARENA + (s * 272 + rm) * 36);
        #pragma unroll
        for (int q = 0; q < 2; q++) {
            ulonglong2 pv = p[q], mv = m[q];
            u64 t0 = mul2(add2(add2(x0p[s][2*q],   pv.x), mv.x), third2);
            u64 t1 = mul2(add2(add2(x0p[s][2*q+1], pv.y), mv.y), third2);
            unpk(t0, a0[s][4*q+0], a0[s][4*q+1]);
            unpk(t1, a0[s][4*q+2], a0[s][4*q+3]);
        }
    }

    // ====== conv1 COMPUTE first (regs+weights only) — hides BAR B skew =======
    u64 x1p[2][8];
    {
        u64 acc[2][8];
        const u64* bb = (const u64*)(sh + B1S);
        #pragma unroll
        for (int j = 0; j < 8; j++) { u64 b = bb[j]; acc[0][j] = b; acc[1][j] = b; }
        #pragma unroll
        for (int k = 0; k < 8; k++) {
            const ulonglong2* w = (const ulonglong2*)(sh + W1S + k * 16);
            #pragma unroll
            for (int q = 0; q < 4; q++) {
                ulonglong2 t = w[q];
                #pragma unroll
                for (int s = 0; s < 2; s++) {
                    u64 av = bcast2(a0[s][k]);
                    acc[s][2*q]   = ffma2(av, t.x, acc[s][2*q]);
                    acc[s][2*q+1] = ffma2(av, t.y, acc[s][2*q+1]);
                }
            }
        }
        #pragma unroll
        for (int s = 0; s < 2; s++)
            #pragma unroll
            for (int j = 0; j < 8; j++) {
                float x, y; unpk(acc[s][j], x, y);
                x1p[s][j] = pack2(fmaxf(x, 0.0f), fmaxf(y, 0.0f));
            }
    }
    __syncthreads();                       // BAR B: x0 reads done (WAR, hidden)
    #pragma unroll
    for (int s = 0; s < 2; s++) {
        ulonglong2* row = (ulonglong2*)(sh + ARENA + (s * 272 + tid) * 36);
        #pragma unroll
        for (int q = 0; q < 4; q++)
            row[q] = make_ulonglong2(x1p[s][2*q], x1p[s][2*q+1]);
    }
    __syncthreads();                       // BAR C: x1 published

    float a1[2][16];
    #pragma unroll
    for (int s = 0; s < 2; s++) {
        const ulonglong2* p = (const ulonglong2*)(sh + ARENA + (s * 272 + rp) * 36);
        const ulonglong2* m = (const ulonglong2*)(sh + ARENA + (s * 272 + rm) * 36);
        #pragma unroll
        for (int q = 0; q < 4; q++) {
            ulonglong2 pv = p[q], mv = m[q];
            u64 t0 = mul2(add2(add2(x1p[s][2*q],   pv.x), mv.x), third2);
            u64 t1 = mul2(add2(add2(x1p[s][2*q+1], pv.y), mv.y), third2);
            unpk(t0, a1[s][4*q+0], a1[s][4*q+1]);
            unpk(t1, a1[s][4*q+2], a1[s][4*q+3]);
        }
    }

    // ====== conv2 COMPUTE (both halves, regs only) — hides BAR D skew ========
    u64 x2p[2][16];
    #pragma unroll
    for (int h = 0; h < 2; h++) {
        u64 acc[2][8];
        const u64* bb = (const u64*)(sh + B2S + h * 16);
        #pragma unroll
        for (int j = 0; j < 8; j++) { u64 b = bb[j]; acc[0][j] = b; acc[1][j] = b; }
        #pragma unroll
        for (int k = 0; k < 16; k++) {
            const ulonglong2* w = (const ulonglong2*)(sh + W2S + k * 32 + h * 16);
            #pragma unroll
            for (int q = 0; q < 4; q++) {
                ulonglong2 t = w[q];
                #pragma unroll
                for (int s = 0; s < 2; s++) {
                    u64 av = bcast2(a1[s][k]);
                    acc[s][2*q]   = ffma2(av, t.x, acc[s][2*q]);
                    acc[s][2*q+1] = ffma2(av, t.y, acc[s][2*q+1]);
                }
            }
        }
        #pragma unroll
        for (int s = 0; s < 2; s++)
            #pragma unroll
            for (int j = 0; j < 8; j++) {
                float x, y; unpk(acc[s][j], x, y);
                x2p[s][h * 8 + j] = pack2(fmaxf(x, 0.0f), fmaxf(y, 0.0f));
            }
    }
    __syncthreads();                       // BAR D: x1 reads done (WAR, hidden)
    #pragma unroll
    for (int s = 0; s < 2; s++) {
        ulonglong2* row = (ulonglong2*)(sh + ARENA + (s * 272 + tid) * 36);
        #pragma unroll
        for (int q = 0; q < 8; q++)
            row[q] = make_ulonglong2(x2p[s][2*q], x2p[s][2*q+1]);
    }
    __syncthreads();                       // BAR E: x2 published

    float a2[2][32];
    #pragma unroll
    for (int s = 0; s < 2; s++) {
        const ulonglong2* p = (const ulonglong2*)(sh + ARENA + (s * 272 + rp) * 36);
        const ulonglong2* m = (const ulonglong2*)(sh + ARENA + (s * 272 + rm) * 36);
        #pragma unroll
        for (int q = 0; q < 8; q++) {
            ulonglong2 pv = p[q], mv = m[q];
            u64 t0 = mul2(add2(add2(x2p[s][2*q],   pv.x), mv.x), third2);
            u64 t1 = mul2(add2(add2(x2p[s][2*q+1], pv.y), mv.y), third2);
            unpk(t0, a2[s][4*q+0], a2[s][4*q+1]);
            unpk(t1, a2[s][4*q+2], a2[s][4*q+3]);
        }
    }

    // ====== conv3: h0 compute hides BAR F (x2 WAR); then stage both halves ===
    #pragma unroll
    for (int h = 0; h < 2; h++) {
        u64 acc[2][8];
        const u64* bb = (const u64*)(sh + B3S + h * 16);
        #pragma unroll
        for (int j = 0; j < 8; j++) { u64 b = bb[j]; acc[0][j] = b; acc[1][j] = b; }
        #pragma unroll
        for (int k = 0; k < 32; k++) {
            const ulonglong2* w = (const ulonglong2*)(sh + W3S + k * 32 + h * 16);
            #pragma unroll
            for (int q = 0; q < 4; q++) {
                ulonglong2 t = w[q];
                #pragma unroll
                for (int s = 0; s < 2; s++) {
                    u64 av = bcast2(a2[s][k]);
                    acc[s][2*q]   = ffma2(av, t.x, acc[s][2*q]);
                    acc[s][2*q+1] = ffma2(av, t.y, acc[s][2*q+1]);
                }
            }
        }
        if (h == 0) __syncthreads();       // BAR F: x2 reads done (WAR, hidden)
        // stage in out layout: row = (g + 16s)*17 + n, columns h*16 .. h*16+15
        #pragma unroll
        for (int s = 0; s < 2; s++) {
            ulonglong2* row = (ulonglong2*)(sh + ARENA + ((g + 16 * s) * 17 + n) * 36 + h * 16);
            #pragma unroll
            for (int q = 0; q < 4; q++)
                row[q] = make_ulonglong2(acc[s][2*q], acc[s][2*q+1]);
        }
    }
    __syncthreads();                       // BAR G: staging published

    // coalesced global write: 32*17*32 floats contiguous per block
    // q = tid + 272*it; 272 = 34*8 -> col (q&7) loop-invariant, row advances 34
    {
        float4* og = (float4*)(out + (size_t)blockIdx.x * (NG * NNODE * 32)) + tid;
        const float* src = sh + ARENA + (tid >> 3) * 36 + (tid & 7) * 4;
        #pragma unroll
        for (int it = 0; it < 16; it++) {
            *og = *(const float4*)src;
            og  += TPB;
            src += 34 * 36;
        }
    }
}

extern "C" void kernel_launch(void* const* d_in, const int* in_sizes, int n_in,
                              void* d_out, int out_size) {
    const float* z    = (const float*)d_in[0];
    // d_in[1] = edge_index: fixed ring, degree==3 everywhere -> norm==1/3; unused
    const float* fc_w = (const float*)d_in[2];
    const float* fc_b = (const float*)d_in[3];
    const float* w1   = (const float*)d_in[4];
    const float* b1   = (const float*)d_in[5];
    const float* w2   = (const float*)d_in[6];
    const float* b2   = (const float*)d_in[7];
    const float* w3   = (const float*)d_in[8];
    const float* b3   = (const float*)d_in[9];

    cudaFuncSetAttribute(gnn_fused, cudaFuncAttributeMaxDynamicSharedMemorySize,
                         SHFLOATS * 4);

    const int B    = in_sizes[0] / 32;      // 65536 graphs
    const int grid = B / NG;                // 2048 blocks
    gnn_fused<<<grid, TPB, SHFLOATS * 4>>>(z, fc_w, fc_b, w1, b1, w2, b2, w3, b3,
                                           (float*)d_out);
}

// round 16
// speedup vs baseline: 2.2615x; 1.3191x over previous
#include <cuda_runtime.h>

#define NNODE 17
#define TPB   272      // 17 nodes x 16 graph-lanes
#define NG    32       // graphs per block: 2 graph-sets per thread (s = 0,1)

typedef unsigned long long u64;

// packed fp32x2 ops (Blackwell); ptxas never auto-fuses these from C++
__device__ __forceinline__ u64 ffma2(u64 a, u64 b, u64 c) {
    u64 d;
    asm("fma.rn.f32x2 %0, %1, %2, %3;" : "=l"(d) : "l"(a), "l"(b), "l"(c));
    return d;
}
__device__ __forceinline__ u64 add2(u64 a, u64 b) {
    u64 d;
    asm("add.rn.f32x2 %0, %1, %2;" : "=l"(d) : "l"(a), "l"(b));
    return d;
}
__device__ __forceinline__ u64 mul2(u64 a, u64 b) {
    u64 d;
    asm("mul.rn.f32x2 %0, %1, %2;" : "=l"(d) : "l"(a), "l"(b));
    return d;
}
__device__ __forceinline__ u64 bcast2(float v) {
    u64 d; unsigned r = __float_as_uint(v);
    asm("mov.b64 %0, {%1, %1};" : "=l"(d) : "r"(r));
    return d;
}
__device__ __forceinline__ u64 pack2(float x, float y) {
    u64 d;
    asm("mov.b64 %0, {%1, %2};" : "=l"(d) : "r"(__float_as_uint(x)), "r"(__float_as_uint(y)));
    return d;
}
__device__ __forceinline__ void unpk(u64 d, float& x, float& y) {
    unsigned a, b;
    asm("mov.b64 {%0, %1}, %2;" : "=r"(a), "=r"(b) : "l"(d));
    x = __uint_as_float(a); y = __uint_as_float(b);
}

// ---- conv weights in CONSTANT memory: separate cache port, off the L1 crossbar
// stored as 16B/8B words; filled by cudaMemcpyToSymbolAsync (D2D, graph-legal).
// Indexed directly (never through casted pointers) so nvcc emits ld.const.
__constant__ ulonglong2 cw1[32];    // w1  8x16 floats  = 512B
__constant__ u64        cb1[8];     // b1  16 floats
__constant__ ulonglong2 cw2[128];   // w2 16x32 floats  = 2KB ; row k = 8 ull2
__constant__ u64        cb2[16];    // b2  32 floats
__constant__ ulonglong2 cw3[256];   // w3 32x32 floats  = 4KB ; row k = 8 ull2
__constant__ u64        cb3[16];    // b3  32 floats

// ---- dynamic shared layout (float offsets) ----
#define FCS   0        // fc_w: 32 rows x 160 (136 used; warp's n-pair in one 128B line)
#define ZS    5120     // 32 graphs x 36
#define ARENA 6272     // 544 rows x 36 floats (exchange + out staging)
#define SHFLOATS 25856 // 103424 bytes per block (x2 blocks = 206.8KB <= 228KB/SM)

extern __shared__ float sh[];

__global__ void __launch_bounds__(TPB, 2)
gnn_fused(const float* __restrict__ z,
          const float* __restrict__ fc_w, const float* __restrict__ fc_b,
          float* __restrict__ out)
{
    const int tid = threadIdx.x;

    // ---------------- stage fc_w + z into shared ----------------
    for (int i = tid; i < 4352; i += TPB) {            // fc_w rows padded 136->160
        int k = i / 136, c = i - k * 136;
        sh[FCS + k * 160 + c] = fc_w[i];
    }
    {
        const float* zblk = z + (size_t)blockIdx.x * (NG * 32);
        for (int i = tid; i < NG * 32; i += TPB)
            sh[ZS + (i >> 5) * 36 + (i & 31)] = zblk[i];
    }
    __syncthreads();                       // BAR 0: init

    // thread = node n, graphs g and g+16; warp holds 2 nodes x 16 lanes
    const int n  = tid >> 4;
    const int g  = tid & 15;
    const int rp = (n == NNODE - 1) ? g       : tid + 16;  // row of node (n+1)%17
    const int rm = (n == 0)         ? 256 + g : tid - 16;  // row of node (n-1)%17
    const u64 third2 = bcast2(1.0f / 3.0f);

    // ================= FC: x0 = z @ fc_w[:, 8n:8n+8] + fc_b ==================
    u64 x0p[2][4];
    {
        float zr[2][32];
        #pragma unroll
        for (int s = 0; s < 2; s++) {
            const float4* zp = (const float4*)(sh + ZS + (g + 16 * s) * 36);
            #pragma unroll
            for (int i = 0; i < 8; i++) {
                float4 v = zp[i];
                zr[s][4*i] = v.x; zr[s][4*i+1] = v.y; zr[s][4*i+2] = v.z; zr[s][4*i+3] = v.w;
            }
        }
        {
            const u64* fb = (const u64*)fc_b + n * 4;
            #pragma unroll
            for (int i = 0; i < 4; i++) { u64 b = __ldg(fb + i); x0p[0][i] = b; x0p[1][i] = b; }
        }
        #pragma unroll
        for (int k = 0; k < 32; k++) {
            const ulonglong2* w = (const ulonglong2*)(sh + FCS + k * 160 + n * 8);
            ulonglong2 wa = w[0], wb = w[1];
            #pragma unroll
            for (int s = 0; s < 2; s++) {
                u64 zz = bcast2(zr[s][k]);
                x0p[s][0] = ffma2(zz, wa.x, x0p[s][0]);
                x0p[s][1] = ffma2(zz, wa.y, x0p[s][1]);
                x0p[s][2] = ffma2(zz, wb.x, x0p[s][2]);
                x0p[s][3] = ffma2(zz, wb.y, x0p[s][3]);
            }
        }
    }
    #pragma unroll
    for (int s = 0; s < 2; s++) {
        ulonglong2* row = (ulonglong2*)(sh + ARENA + (s * 272 + tid) * 36);
        row[0] = make_ulonglong2(x0p[s][0], x0p[s][1]);
        row[1] = make_ulonglong2(x0p[s][2], x0p[s][3]);
    }
    __syncthreads();                       // BAR A: x0 published
    float a0[2][8];
    #pragma unroll
    for (int s = 0; s < 2; s++) {
        const ulonglong2* p = (const ulonglong2*)(sh + ARENA + (s * 272 + rp) * 36);
        const ulonglong2* m = (const ulonglong2*)(sh + ARENA + (s * 272 + rm) * 36);
        #pragma unroll
        for (int q = 0; q < 2; q++) {
            ulonglong2 pv = p[q], mv = m[q];
            u64 t0 = mul2(add2(add2(x0p[s][2*q],   pv.x), mv.x), third2);
            u64 t1 = mul2(add2(add2(x0p[s][2*q+1], pv.y), mv.y), third2);
            unpk(t0, a0[s][4*q+0], a0[s][4*q+1]);
            unpk(t1, a0[s][4*q+2], a0[s][4*q+3]);
        }
    }
    __syncthreads();                       // BAR B: x0 reads done (WAR)

    // ================= conv1: x1 = relu(a0 @ w1 + b1), 16 out =================
    u64 x1p[2][8];
    {
        u64 acc[2][8];
        #pragma unroll
        for (int j = 0; j < 8; j++) { u64 b = cb1[j]; acc[0][j] = b; acc[1][j] = b; }
        #pragma unroll
        for (int k = 0; k < 8; k++) {
            #pragma unroll
            for (int q = 0; q < 4; q++) {
                ulonglong2 t = cw1[k * 4 + q];
                #pragma unroll
                for (int s = 0; s < 2; s++) {
                    u64 av = bcast2(a0[s][k]);
                    acc[s][2*q]   = ffma2(av, t.x, acc[s][2*q]);
                    acc[s][2*q+1] = ffma2(av, t.y, acc[s][2*q+1]);
                }
            }
        }
        #pragma unroll
        for (int s = 0; s < 2; s++)
            #pragma unroll
            for (int j = 0; j < 8; j++) {
                float x, y; unpk(acc[s][j], x, y);
                x1p[s][j] = pack2(fmaxf(x, 0.0f), fmaxf(y, 0.0f));
            }
    }
    #pragma unroll
    for (int s = 0; s < 2; s++) {
        ulonglong2* row = (ulonglong2*)(sh + ARENA + (s * 272 + tid) * 36);
        #pragma unroll
        for (int q = 0; q < 4; q++)
            row[q] = make_ulonglong2(x1p[s][2*q], x1p[s][2*q+1]);
    }
    __syncthreads();                       // BAR C: x1 published
    float a1[2][16];
    #pragma unroll
    for (int s = 0; s < 2; s++) {
        const ulonglong2* p = (const ulonglong2*)(sh + ARENA + (s * 272 + rp) * 36);
        const ulonglong2* m = (const ulonglong2*)(sh + ARENA + (s * 272 + rm) * 36);
        #pragma unroll
        for (int q = 0; q < 4; q++) {
            ulonglong2 pv = p[q], mv = m[q];
            u64 t0 = mul2(add2(add2(x1p[s][2*q],   pv.x), mv.x), third2);
            u64 t1 = mul2(add2(add2(x1p[s][2*q+1], pv.y), mv.y), third2);
            unpk(t0, a1[s][4*q+0], a1[s][4*q+1]);
            unpk(t1, a1[s][4*q+2], a1[s][4*q+3]);
        }
    }
    __syncthreads();                       // BAR D: x1 reads done (WAR)

    // ====== conv2: x2 = relu(a1 @ w2 + b2), 32 out, j-halves ==================
    u64 x2p[2][16];
    #pragma unroll
    for (int h = 0; h < 2; h++) {
        u64 acc[2][8];
        #pragma unroll
        for (int j = 0; j < 8; j++) { u64 b = cb2[h * 8 + j]; acc[0][j] = b; acc[1][j] = b; }
        #pragma unroll
        for (int k = 0; k < 16; k++) {
            #pragma unroll
            for (int q = 0; q < 4; q++) {
                ulonglong2 t = cw2[k * 8 + h * 4 + q];
                #pragma unroll
                for (int s = 0; s < 2; s++) {
                    u64 av = bcast2(a1[s][k]);
                    acc[s][2*q]   = ffma2(av, t.x, acc[s][2*q]);
                    acc[s][2*q+1] = ffma2(av, t.y, acc[s][2*q+1]);
                }
            }
        }
        #pragma unroll
        for (int s = 0; s < 2; s++) {
            #pragma unroll
            for (int j = 0; j < 8; j++) {
                float x, y; unpk(acc[s][j], x, y);
                x2p[s][h * 8 + j] = pack2(fmaxf(x, 0.0f), fmaxf(y, 0.0f));
            }
            ulonglong2* row = (ulonglong2*)(sh + ARENA + (s * 272 + tid) * 36 + h * 16);
            #pragma unroll
            for (int q = 0; q < 4; q++)
                row[q] = make_ulonglong2(x2p[s][h*8 + 2*q], x2p[s][h*8 + 2*q + 1]);
        }
    }
    __syncthreads();                       // BAR E: x2 published
    float a2[2][32];
    #pragma unroll
    for (int s = 0; s < 2; s++) {
        const ulonglong2* p = (const ulonglong2*)(sh + ARENA + (s * 272 + rp) * 36);
        const ulonglong2* m = (const ulonglong2*)(sh + ARENA + (s * 272 + rm) * 36);
        #pragma unroll
        for (int q = 0; q < 8; q++) {
            ulonglong2 pv = p[q], mv = m[q];
            u64 t0 = mul2(add2(add2(x2p[s][2*q],   pv.x), mv.x), third2);
            u64 t1 = mul2(add2(add2(x2p[s][2*q+1], pv.y), mv.y), third2);
            unpk(t0, a2[s][4*q+0], a2[s][4*q+1]);
            unpk(t1, a2[s][4*q+2], a2[s][4*q+3]);
        }
    }
    __syncthreads();                       // BAR F: x2 reads done; arena reused

    // ====== conv3: out = a2 @ w3 + b3, j-halves, stage to arena ===============
    #pragma unroll
    for (int h = 0; h < 2; h++) {
        u64 acc[2][8];
        #pragma unroll
        for (int j = 0; j < 8; j++) { u64 b = cb3[h * 8 + j]; acc[0][j] = b; acc[1][j] = b; }
        #pragma unroll
        for (int k = 0; k < 32; k++) {
            #pragma unroll
            for (int q = 0; q < 4; q++) {
                ulonglong2 t = cw3[k * 8 + h * 4 + q];
                #pragma unroll
                for (int s = 0; s < 2; s++) {
                    u64 av = bcast2(a2[s][k]);
                    acc[s][2*q]   = ffma2(av, t.x, acc[s][2*q]);
                    acc[s][2*q+1] = ffma2(av, t.y, acc[s][2*q+1]);
                }
            }
        }
        // stage in out layout: row = (g + 16s)*17 + n, columns h*16 .. h*16+15
        #pragma unroll
        for (int s = 0; s < 2; s++) {
            ulonglong2* row = (ulonglong2*)(sh + ARENA + ((g + 16 * s) * 17 + n) * 36 + h * 16);
            #pragma unroll
            for (int q = 0; q < 4; q++)
                row[q] = make_ulonglong2(acc[s][2*q], acc[s][2*q+1]);
        }
    }
    __syncthreads();                       // BAR G: staging published

    // coalesced global write: 32*17*32 floats contiguous per block
    float4* og = (float4*)(out + (size_t)blockIdx.x * (NG * NNODE * 32));
    #pragma unroll
    for (int it = 0; it < 16; it++) {
        int q = tid + it * TPB;                 // 0 .. 4351
        int row = q >> 3, c = q & 7;
        og[q] = *(const float4*)(sh + ARENA + row * 36 + c * 4);
    }
}

extern "C" void kernel_launch(void* const* d_in, const int* in_sizes, int n_in,
                              void* d_out, int out_size) {
    const float* z    = (const float*)d_in[0];
    // d_in[1] = edge_index: fixed ring, degree==3 everywhere -> norm==1/3; unused
    const float* fc_w = (const float*)d_in[2];
    const float* fc_b = (const float*)d_in[3];

    // conv weights -> constant bank (async D2D copies: graph-capturable)
    cudaMemcpyToSymbolAsync(cw1, d_in[4], 128  * 4, 0, cudaMemcpyDeviceToDevice, 0);
    cudaMemcpyToSymbolAsync(cb1, d_in[5], 16   * 4, 0, cudaMemcpyDeviceToDevice, 0);
    cudaMemcpyToSymbolAsync(cw2, d_in[6], 512  * 4, 0, cudaMemcpyDeviceToDevice, 0);
    cudaMemcpyToSymbolAsync(cb2, d_in[7], 32   * 4, 0, cudaMemcpyDeviceToDevice, 0);
    cudaMemcpyToSymbolAsync(cw3, d_in[8], 1024 * 4, 0, cudaMemcpyDeviceToDevice, 0);
    cudaMemcpyToSymbolAsync(cb3, d_in[9], 32   * 4, 0, cudaMemcpyDeviceToDevice, 0);

    cudaFuncSetAttribute(gnn_fused, cudaFuncAttributeMaxDynamicSharedMemorySize,
                         SHFLOATS * 4);

    const int B    = in_sizes[0] / 32;      // 65536 graphs
    const int grid = B / NG;                // 2048 blocks
    gnn_fused<<<grid, TPB, SHFLOATS * 4>>>(z, fc_w, fc_b, (float*)d_out);
}